// round 1
// baseline (speedup 1.0000x reference)
#include <cuda_runtime.h>
#include <cuda_bf16.h>
#include <math_constants.h>

// MASS_18897856102446: fused weighted-sq-dist attention
// out[b,n] = out_dist[b,n] * softmax_n(-(att_dist[b,n]*mask[b,n]))
// B=1024, N=200, E=128 (fp32). HBM-bound: m + m_c = ~210MB streamed once.

constexpr int N_ = 200;
constexpr int E_ = 128;
constexpr int NWARP = 8;
constexpr int NTHR = NWARP * 32;

__global__ __launch_bounds__(NTHR, 4)
void mass_kernel(const float* __restrict__ q,
                 const float* __restrict__ q_p,
                 const float* __restrict__ m,
                 const float* __restrict__ m_c,
                 const float* __restrict__ A1,
                 const float* __restrict__ A2,
                 const float* __restrict__ biases,
                 const float* __restrict__ mask,
                 float* __restrict__ out)
{
    const int b    = blockIdx.x;
    const int tid  = threadIdx.x;
    const int warp = tid >> 5;
    const int lane = tid & 31;

    __shared__ float4 s_a1[E_ / 4], s_a2[E_ / 4], s_qa1[E_ / 4], s_qpa2[E_ / 4];
    __shared__ float  s_logit[N_], s_outd[N_];
    __shared__ float  s_red[NWARP];

    // Stage per-batch vectors; fold q into q*A so the inner loop is pure FMA on m.
    if (tid < E_) {
        float a1 = A1[tid];
        float a2 = A2[tid];
        reinterpret_cast<float*>(s_a1)[tid]   = a1;
        reinterpret_cast<float*>(s_a2)[tid]   = a2;
        reinterpret_cast<float*>(s_qa1)[tid]  = q  [(size_t)b * E_ + tid] * a1;
        reinterpret_cast<float*>(s_qpa2)[tid] = q_p[(size_t)b * E_ + tid] * a2;
    }
    __syncthreads();

    // Each lane owns elements e = lane*4 .. lane*4+3 of every row.
    const float4 a1v = s_a1[lane];
    const float4 a2v = s_a2[lane];
    const float4 qa  = s_qa1[lane];
    const float4 qp  = s_qpa2[lane];

    const float4* __restrict__ m4 = reinterpret_cast<const float4*>(m   + (size_t)b * N_ * E_);
    const float4* __restrict__ c4 = reinterpret_cast<const float4*>(m_c + (size_t)b * N_ * E_);
    const float*  __restrict__ bia = biases + (size_t)b * N_;
    const float*  __restrict__ msk = mask   + (size_t)b * N_;

    // One warp per row; 25 rows per warp. Two independent float4 loads per row.
    for (int n = warp; n < N_; n += NWARP) {
        const float4 mv = m4[n * (E_ / 4) + lane];
        const float4 cv = c4[n * (E_ / 4) + lane];

        float sa = 0.f, so = 0.f, d;
        // att: against m, both metrics
        d = qa.x - mv.x * a1v.x; sa += d * d;
        d = qa.y - mv.y * a1v.y; sa += d * d;
        d = qa.z - mv.z * a1v.z; sa += d * d;
        d = qa.w - mv.w * a1v.w; sa += d * d;
        d = qp.x - mv.x * a2v.x; sa += d * d;
        d = qp.y - mv.y * a2v.y; sa += d * d;
        d = qp.z - mv.z * a2v.z; sa += d * d;
        d = qp.w - mv.w * a2v.w; sa += d * d;
        // out: against m_c, both metrics
        d = qa.x - cv.x * a1v.x; so += d * d;
        d = qa.y - cv.y * a1v.y; so += d * d;
        d = qa.z - cv.z * a1v.z; so += d * d;
        d = qa.w - cv.w * a1v.w; so += d * d;
        d = qp.x - cv.x * a2v.x; so += d * d;
        d = qp.y - cv.y * a2v.y; so += d * d;
        d = qp.z - cv.z * a2v.z; so += d * d;
        d = qp.w - cv.w * a2v.w; so += d * d;

        #pragma unroll
        for (int o = 16; o; o >>= 1) {
            sa += __shfl_xor_sync(0xffffffffu, sa, o);
            so += __shfl_xor_sync(0xffffffffu, so, o);
        }
        if (lane == 0) {
            const float b2 = 2.f * bia[n];
            const float mk = msk[n];
            s_logit[n] = -((sa + b2) * mk);
            s_outd[n]  = (so + b2) * mk;
        }
    }
    __syncthreads();

    // Block softmax over N_=200 (threads 200..255 idle-but-participating).
    const float v = (tid < N_) ? s_logit[tid] : -CUDART_INF_F;

    float wm = v;
    #pragma unroll
    for (int o = 16; o; o >>= 1)
        wm = fmaxf(wm, __shfl_xor_sync(0xffffffffu, wm, o));
    if (lane == 0) s_red[warp] = wm;
    __syncthreads();

    float mx = s_red[0];
    #pragma unroll
    for (int i = 1; i < NWARP; i++) mx = fmaxf(mx, s_red[i]);

    const float ex = (tid < N_) ? __expf(v - mx) : 0.f;

    float ws = ex;
    #pragma unroll
    for (int o = 16; o; o >>= 1)
        ws += __shfl_xor_sync(0xffffffffu, ws, o);
    __syncthreads();              // everyone has read s_red for max
    if (lane == 0) s_red[warp] = ws;
    __syncthreads();

    float tot = s_red[0];
    #pragma unroll
    for (int i = 1; i < NWARP; i++) tot += s_red[i];
    const float inv = 1.f / tot;

    if (tid < N_)
        out[(size_t)b * N_ + tid] = s_outd[tid] * ex * inv;
}

extern "C" void kernel_launch(void* const* d_in, const int* in_sizes, int n_in,
                              void* d_out, int out_size)
{
    const float* q      = (const float*)d_in[0];
    const float* q_p    = (const float*)d_in[1];
    const float* m      = (const float*)d_in[2];
    const float* m_c    = (const float*)d_in[3];
    const float* A1     = (const float*)d_in[4];
    const float* A2     = (const float*)d_in[5];
    const float* biases = (const float*)d_in[6];
    const float* mask   = (const float*)d_in[7];
    float* out = (float*)d_out;

    const int B = in_sizes[0] / E_;   // 1024
    mass_kernel<<<B, NTHR>>>(q, q_p, m, m_c, A1, A2, biases, mask, out);
}

// round 2
// speedup vs baseline: 1.2370x; 1.2370x over previous
#include <cuda_runtime.h>
#include <cuda_bf16.h>
#include <math_constants.h>

// MASS_18897856102446: fused weighted-sq-dist attention
// out[b,n] = out_dist[b,n] * softmax_n(-(att_dist[b,n]*mask[b,n]))
// B=1024, N=200, E=128 (fp32). HBM-bound: m + m_c = ~210MB streamed once.
// R2: 4-row unroll per warp iteration -> MLP 2->8 per warp to cover DRAM latency.

constexpr int N_ = 200;
constexpr int E_ = 128;
constexpr int NWARP = 8;
constexpr int NTHR = NWARP * 32;

__global__ __launch_bounds__(NTHR)
void mass_kernel(const float* __restrict__ q,
                 const float* __restrict__ q_p,
                 const float* __restrict__ m,
                 const float* __restrict__ m_c,
                 const float* __restrict__ A1,
                 const float* __restrict__ A2,
                 const float* __restrict__ biases,
                 const float* __restrict__ mask,
                 float* __restrict__ out)
{
    const int b    = blockIdx.x;
    const int tid  = threadIdx.x;
    const int warp = tid >> 5;
    const int lane = tid & 31;

    __shared__ float4 s_a1[E_ / 4], s_a2[E_ / 4], s_qa1[E_ / 4], s_qpa2[E_ / 4];
    __shared__ float  s_logit[N_], s_outd[N_];
    __shared__ float  s_red[NWARP];

    if (tid < E_) {
        float a1 = A1[tid];
        float a2 = A2[tid];
        reinterpret_cast<float*>(s_a1)[tid]   = a1;
        reinterpret_cast<float*>(s_a2)[tid]   = a2;
        reinterpret_cast<float*>(s_qa1)[tid]  = q  [(size_t)b * E_ + tid] * a1;
        reinterpret_cast<float*>(s_qpa2)[tid] = q_p[(size_t)b * E_ + tid] * a2;
    }
    __syncthreads();

    const float4 a1v = s_a1[lane];
    const float4 a2v = s_a2[lane];
    const float4 qa  = s_qa1[lane];
    const float4 qp  = s_qpa2[lane];

    const float4* __restrict__ m4 = reinterpret_cast<const float4*>(m   + (size_t)b * N_ * E_);
    const float4* __restrict__ c4 = reinterpret_cast<const float4*>(m_c + (size_t)b * N_ * E_);
    const float*  __restrict__ bia = biases + (size_t)b * N_;
    const float*  __restrict__ msk = mask   + (size_t)b * N_;

    // Per-row body: given mv/cv, produce per-lane partial (sa, so).
    auto body = [&](const float4 mv, const float4 cv, float& sa, float& so) {
        float d;
        d = qa.x - mv.x * a1v.x; sa  = d * d;
        d = qa.y - mv.y * a1v.y; sa += d * d;
        d = qa.z - mv.z * a1v.z; sa += d * d;
        d = qa.w - mv.w * a1v.w; sa += d * d;
        d = qp.x - mv.x * a2v.x; sa += d * d;
        d = qp.y - mv.y * a2v.y; sa += d * d;
        d = qp.z - mv.z * a2v.z; sa += d * d;
        d = qp.w - mv.w * a2v.w; sa += d * d;
        d = qa.x - cv.x * a1v.x; so  = d * d;
        d = qa.y - cv.y * a1v.y; so += d * d;
        d = qa.z - cv.z * a1v.z; so += d * d;
        d = qa.w - cv.w * a1v.w; so += d * d;
        d = qp.x - cv.x * a2v.x; so += d * d;
        d = qp.y - cv.y * a2v.y; so += d * d;
        d = qp.z - cv.z * a2v.z; so += d * d;
        d = qp.w - cv.w * a2v.w; so += d * d;
    };

    auto finish = [&](int n, float sa, float so) {
        if (lane == 0) {
            const float b2 = 2.f * bia[n];
            const float mk = msk[n];
            s_logit[n] = -((sa + b2) * mk);
            s_outd[n]  = (so + b2) * mk;
        }
    };

    // 25 rows per warp (stride NWARP). Unroll 4 rows: 8 independent float4
    // loads in flight, 8 interleaved shuffle-reduction chains.
    #pragma unroll 1
    for (int k = 0; k < 24; k += 4) {
        const int n0 = warp + (k + 0) * NWARP;
        const int n1 = warp + (k + 1) * NWARP;
        const int n2 = warp + (k + 2) * NWARP;
        const int n3 = warp + (k + 3) * NWARP;

        // Batch all 8 loads up front (front-batched MLP).
        const float4 mv0 = m4[n0 * (E_ / 4) + lane];
        const float4 mv1 = m4[n1 * (E_ / 4) + lane];
        const float4 mv2 = m4[n2 * (E_ / 4) + lane];
        const float4 mv3 = m4[n3 * (E_ / 4) + lane];
        const float4 cv0 = c4[n0 * (E_ / 4) + lane];
        const float4 cv1 = c4[n1 * (E_ / 4) + lane];
        const float4 cv2 = c4[n2 * (E_ / 4) + lane];
        const float4 cv3 = c4[n3 * (E_ / 4) + lane];

        float sa0, so0, sa1, so1, sa2, so2, sa3, so3;
        body(mv0, cv0, sa0, so0);
        body(mv1, cv1, sa1, so1);
        body(mv2, cv2, sa2, so2);
        body(mv3, cv3, sa3, so3);

        // 8 interleaved reduction chains — shuffle latency overlaps.
        #pragma unroll
        for (int o = 16; o; o >>= 1) {
            sa0 += __shfl_xor_sync(0xffffffffu, sa0, o);
            so0 += __shfl_xor_sync(0xffffffffu, so0, o);
            sa1 += __shfl_xor_sync(0xffffffffu, sa1, o);
            so1 += __shfl_xor_sync(0xffffffffu, so1, o);
            sa2 += __shfl_xor_sync(0xffffffffu, sa2, o);
            so2 += __shfl_xor_sync(0xffffffffu, so2, o);
            sa3 += __shfl_xor_sync(0xffffffffu, sa3, o);
            so3 += __shfl_xor_sync(0xffffffffu, so3, o);
        }
        finish(n0, sa0, so0);
        finish(n1, sa1, so1);
        finish(n2, sa2, so2);
        finish(n3, sa3, so3);
    }
    // Tail row (k = 24): n = warp + 192
    {
        const int n = warp + 24 * NWARP;
        const float4 mv = m4[n * (E_ / 4) + lane];
        const float4 cv = c4[n * (E_ / 4) + lane];
        float sa, so;
        body(mv, cv, sa, so);
        #pragma unroll
        for (int o = 16; o; o >>= 1) {
            sa += __shfl_xor_sync(0xffffffffu, sa, o);
            so += __shfl_xor_sync(0xffffffffu, so, o);
        }
        finish(n, sa, so);
    }
    __syncthreads();

    // Block softmax over N_=200.
    const float v = (tid < N_) ? s_logit[tid] : -CUDART_INF_F;

    float wm = v;
    #pragma unroll
    for (int o = 16; o; o >>= 1)
        wm = fmaxf(wm, __shfl_xor_sync(0xffffffffu, wm, o));
    if (lane == 0) s_red[warp] = wm;
    __syncthreads();

    float mx = s_red[0];
    #pragma unroll
    for (int i = 1; i < NWARP; i++) mx = fmaxf(mx, s_red[i]);

    const float ex = (tid < N_) ? __expf(v - mx) : 0.f;

    float ws = ex;
    #pragma unroll
    for (int o = 16; o; o >>= 1)
        ws += __shfl_xor_sync(0xffffffffu, ws, o);
    __syncthreads();
    if (lane == 0) s_red[warp] = ws;
    __syncthreads();

    float tot = s_red[0];
    #pragma unroll
    for (int i = 1; i < NWARP; i++) tot += s_red[i];
    const float inv = 1.f / tot;

    if (tid < N_)
        out[(size_t)b * N_ + tid] = s_outd[tid] * ex * inv;
}

extern "C" void kernel_launch(void* const* d_in, const int* in_sizes, int n_in,
                              void* d_out, int out_size)
{
    const float* q      = (const float*)d_in[0];
    const float* q_p    = (const float*)d_in[1];
    const float* m      = (const float*)d_in[2];
    const float* m_c    = (const float*)d_in[3];
    const float* A1     = (const float*)d_in[4];
    const float* A2     = (const float*)d_in[5];
    const float* biases = (const float*)d_in[6];
    const float* mask   = (const float*)d_in[7];
    float* out = (float*)d_out;

    const int B = in_sizes[0] / E_;   // 1024
    mass_kernel<<<B, NTHR>>>(q, q_p, m, m_c, A1, A2, biases, mask, out);
}

// round 3
// speedup vs baseline: 1.3238x; 1.0702x over previous
#include <cuda_runtime.h>
#include <cuda_bf16.h>
#include <math_constants.h>

// MASS_18897856102446: fused weighted-sq-dist attention
// out[b,n] = out_dist[b,n] * softmax_n(-(att_dist[b,n]*mask[b,n]))
// B=1024, N=200, E=128 (fp32). HBM-bound: m + m_c = ~210MB streamed once.
// R3: 8-row unroll per warp iteration -> 16 float4 loads in flight per warp.

constexpr int N_ = 200;
constexpr int E_ = 128;
constexpr int NWARP = 8;
constexpr int NTHR = NWARP * 32;

__global__ __launch_bounds__(NTHR)
void mass_kernel(const float* __restrict__ q,
                 const float* __restrict__ q_p,
                 const float* __restrict__ m,
                 const float* __restrict__ m_c,
                 const float* __restrict__ A1,
                 const float* __restrict__ A2,
                 const float* __restrict__ biases,
                 const float* __restrict__ mask,
                 float* __restrict__ out)
{
    const int b    = blockIdx.x;
    const int tid  = threadIdx.x;
    const int warp = tid >> 5;
    const int lane = tid & 31;

    __shared__ float4 s_a1[E_ / 4], s_a2[E_ / 4], s_qa1[E_ / 4], s_qpa2[E_ / 4];
    __shared__ float  s_logit[N_], s_outd[N_];
    __shared__ float  s_red[NWARP];

    if (tid < E_) {
        float a1 = A1[tid];
        float a2 = A2[tid];
        reinterpret_cast<float*>(s_a1)[tid]   = a1;
        reinterpret_cast<float*>(s_a2)[tid]   = a2;
        reinterpret_cast<float*>(s_qa1)[tid]  = q  [(size_t)b * E_ + tid] * a1;
        reinterpret_cast<float*>(s_qpa2)[tid] = q_p[(size_t)b * E_ + tid] * a2;
    }
    __syncthreads();

    const float4 a1v = s_a1[lane];
    const float4 a2v = s_a2[lane];
    const float4 qa  = s_qa1[lane];
    const float4 qp  = s_qpa2[lane];

    const float4* __restrict__ m4 = reinterpret_cast<const float4*>(m   + (size_t)b * N_ * E_);
    const float4* __restrict__ c4 = reinterpret_cast<const float4*>(m_c + (size_t)b * N_ * E_);
    const float*  __restrict__ bia = biases + (size_t)b * N_;
    const float*  __restrict__ msk = mask   + (size_t)b * N_;

    auto body = [&](const float4 mv, const float4 cv, float& sa, float& so) {
        float d;
        d = qa.x - mv.x * a1v.x; sa  = d * d;
        d = qa.y - mv.y * a1v.y; sa += d * d;
        d = qa.z - mv.z * a1v.z; sa += d * d;
        d = qa.w - mv.w * a1v.w; sa += d * d;
        d = qp.x - mv.x * a2v.x; sa += d * d;
        d = qp.y - mv.y * a2v.y; sa += d * d;
        d = qp.z - mv.z * a2v.z; sa += d * d;
        d = qp.w - mv.w * a2v.w; sa += d * d;
        d = qa.x - cv.x * a1v.x; so  = d * d;
        d = qa.y - cv.y * a1v.y; so += d * d;
        d = qa.z - cv.z * a1v.z; so += d * d;
        d = qa.w - cv.w * a1v.w; so += d * d;
        d = qp.x - cv.x * a2v.x; so += d * d;
        d = qp.y - cv.y * a2v.y; so += d * d;
        d = qp.z - cv.z * a2v.z; so += d * d;
        d = qp.w - cv.w * a2v.w; so += d * d;
    };

    auto finish = [&](int n, float sa, float so) {
        if (lane == 0) {
            const float b2 = 2.f * bia[n];
            const float mk = msk[n];
            s_logit[n] = -((sa + b2) * mk);
            s_outd[n]  = (so + b2) * mk;
        }
    };

    // 25 rows per warp. Unroll 8 rows: 16 independent float4 loads in flight.
    #pragma unroll 1
    for (int k = 0; k < 24; k += 8) {
        int n0 = warp + (k + 0) * NWARP;
        int n1 = warp + (k + 1) * NWARP;
        int n2 = warp + (k + 2) * NWARP;
        int n3 = warp + (k + 3) * NWARP;
        int n4 = warp + (k + 4) * NWARP;
        int n5 = warp + (k + 5) * NWARP;
        int n6 = warp + (k + 6) * NWARP;
        int n7 = warp + (k + 7) * NWARP;

        // Front-batch all 16 loads.
        const float4 mv0 = m4[n0 * (E_ / 4) + lane];
        const float4 mv1 = m4[n1 * (E_ / 4) + lane];
        const float4 mv2 = m4[n2 * (E_ / 4) + lane];
        const float4 mv3 = m4[n3 * (E_ / 4) + lane];
        const float4 mv4 = m4[n4 * (E_ / 4) + lane];
        const float4 mv5 = m4[n5 * (E_ / 4) + lane];
        const float4 mv6 = m4[n6 * (E_ / 4) + lane];
        const float4 mv7 = m4[n7 * (E_ / 4) + lane];
        const float4 cv0 = c4[n0 * (E_ / 4) + lane];
        const float4 cv1 = c4[n1 * (E_ / 4) + lane];
        const float4 cv2 = c4[n2 * (E_ / 4) + lane];
        const float4 cv3 = c4[n3 * (E_ / 4) + lane];
        const float4 cv4 = c4[n4 * (E_ / 4) + lane];
        const float4 cv5 = c4[n5 * (E_ / 4) + lane];
        const float4 cv6 = c4[n6 * (E_ / 4) + lane];
        const float4 cv7 = c4[n7 * (E_ / 4) + lane];

        float sa0, so0, sa1, so1, sa2, so2, sa3, so3;
        float sa4, so4, sa5, so5, sa6, so6, sa7, so7;
        body(mv0, cv0, sa0, so0);
        body(mv1, cv1, sa1, so1);
        body(mv2, cv2, sa2, so2);
        body(mv3, cv3, sa3, so3);
        body(mv4, cv4, sa4, so4);
        body(mv5, cv5, sa5, so5);
        body(mv6, cv6, sa6, so6);
        body(mv7, cv7, sa7, so7);

        #pragma unroll
        for (int o = 16; o; o >>= 1) {
            sa0 += __shfl_xor_sync(0xffffffffu, sa0, o);
            so0 += __shfl_xor_sync(0xffffffffu, so0, o);
            sa1 += __shfl_xor_sync(0xffffffffu, sa1, o);
            so1 += __shfl_xor_sync(0xffffffffu, so1, o);
            sa2 += __shfl_xor_sync(0xffffffffu, sa2, o);
            so2 += __shfl_xor_sync(0xffffffffu, so2, o);
            sa3 += __shfl_xor_sync(0xffffffffu, sa3, o);
            so3 += __shfl_xor_sync(0xffffffffu, so3, o);
            sa4 += __shfl_xor_sync(0xffffffffu, sa4, o);
            so4 += __shfl_xor_sync(0xffffffffu, so4, o);
            sa5 += __shfl_xor_sync(0xffffffffu, sa5, o);
            so5 += __shfl_xor_sync(0xffffffffu, so5, o);
            sa6 += __shfl_xor_sync(0xffffffffu, sa6, o);
            so6 += __shfl_xor_sync(0xffffffffu, so6, o);
            sa7 += __shfl_xor_sync(0xffffffffu, sa7, o);
            so7 += __shfl_xor_sync(0xffffffffu, so7, o);
        }
        finish(n0, sa0, so0);
        finish(n1, sa1, so1);
        finish(n2, sa2, so2);
        finish(n3, sa3, so3);
        finish(n4, sa4, so4);
        finish(n5, sa5, so5);
        finish(n6, sa6, so6);
        finish(n7, sa7, so7);
    }
    // Tail row: n = warp + 192
    {
        const int n = warp + 24 * NWARP;
        const float4 mv = m4[n * (E_ / 4) + lane];
        const float4 cv = c4[n * (E_ / 4) + lane];
        float sa, so;
        body(mv, cv, sa, so);
        #pragma unroll
        for (int o = 16; o; o >>= 1) {
            sa += __shfl_xor_sync(0xffffffffu, sa, o);
            so += __shfl_xor_sync(0xffffffffu, so, o);
        }
        finish(n, sa, so);
    }
    __syncthreads();

    // Block softmax over N_=200.
    const float v = (tid < N_) ? s_logit[tid] : -CUDART_INF_F;

    float wm = v;
    #pragma unroll
    for (int o = 16; o; o >>= 1)
        wm = fmaxf(wm, __shfl_xor_sync(0xffffffffu, wm, o));
    if (lane == 0) s_red[warp] = wm;
    __syncthreads();

    float mx = s_red[0];
    #pragma unroll
    for (int i = 1; i < NWARP; i++) mx = fmaxf(mx, s_red[i]);

    const float ex = (tid < N_) ? __expf(v - mx) : 0.f;

    float ws = ex;
    #pragma unroll
    for (int o = 16; o; o >>= 1)
        ws += __shfl_xor_sync(0xffffffffu, ws, o);
    __syncthreads();
    if (lane == 0) s_red[warp] = ws;
    __syncthreads();

    float tot = s_red[0];
    #pragma unroll
    for (int i = 1; i < NWARP; i++) tot += s_red[i];
    const float inv = 1.f / tot;

    if (tid < N_)
        out[(size_t)b * N_ + tid] = s_outd[tid] * ex * inv;
}

extern "C" void kernel_launch(void* const* d_in, const int* in_sizes, int n_in,
                              void* d_out, int out_size)
{
    const float* q      = (const float*)d_in[0];
    const float* q_p    = (const float*)d_in[1];
    const float* m      = (const float*)d_in[2];
    const float* m_c    = (const float*)d_in[3];
    const float* A1     = (const float*)d_in[4];
    const float* A2     = (const float*)d_in[5];
    const float* biases = (const float*)d_in[6];
    const float* mask   = (const float*)d_in[7];
    float* out = (float*)d_out;

    const int B = in_sizes[0] / E_;   // 1024
    mass_kernel<<<B, NTHR>>>(q, q_p, m, m_c, A1, A2, biases, mask, out);
}